// round 4
// baseline (speedup 1.0000x reference)
#include <cuda_runtime.h>
#include <cstdint>
#include <cstddef>

#define NN 100000
#define NE 1600000
#define NH 4
#define DI 128
#define DO 32

// -------- scratch (no allocs allowed) --------
__device__ float    g_Hw[(size_t)NH * NN * DO];   // [h][n][o]  51.2 MB
__device__ float    g_ssrc[NH * NN];              // [h][n]
__device__ float    g_stgt[NH * NN];
__device__ unsigned g_segmax[NH * NN];            // monotonic-uint encoded float max
__device__ float    g_segsum[NH * NN];
__device__ float    g_Ee[(size_t)NE * NH];        // per-edge [e][h] logits -> exp  25.6 MB

__device__ __forceinline__ int clampN(int v) {
    v = v < 0 ? 0 : v;
    return v >= NN ? NN - 1 : v;
}

// monotonic float<->uint order-preserving encoding (for atomicMax on floats incl. negatives)
__device__ __forceinline__ unsigned f_enc(float f) {
    unsigned u = __float_as_uint(f);
    return (u & 0x80000000u) ? ~u : (u | 0x80000000u);
}
__device__ __forceinline__ float f_dec(unsigned u) {
    return __uint_as_float((u & 0x80000000u) ? (u ^ 0x80000000u) : ~u);
}

// -------- kernel 0: zero init (d_out is poisoned, atomics need zeros) --------
__global__ void k_init(float* __restrict__ out) {
    int stride = gridDim.x * blockDim.x;
    int i0 = blockIdx.x * blockDim.x + threadIdx.x;
    for (int i = i0; i < NH * NN; i += stride) {
        g_segmax[i] = 0u;     // decodes below any finite float
        g_segsum[i] = 0.0f;
    }
    const int total = NH * NN * DO;
    for (int i = i0; i < total; i += stride) out[i] = 0.0f;
}

// -------- kernel A: H_w = H_in @ W^T (per head) + fused s_src/s_tgt --------
// grid.x = ceil(NN/64), grid.y = 2 (head pair). 256 threads.
#define TBN 64
#define WS_STRIDE 68
__global__ __launch_bounds__(256) void k_gemm(const float* __restrict__ Hin,
                                              const float* __restrict__ W,
                                              const float* __restrict__ Asrc,
                                              const float* __restrict__ Atgt) {
    extern __shared__ float sm[];
    float* ws = sm;                     // [DI][WS_STRIDE] (uses first 64 cols)
    float* hs = sm + DI * WS_STRIDE;    // [TBN][DI]

    const int t  = threadIdx.x;
    const int tx = t & 15;              // output quad index (j = tx*4)
    const int ty = t >> 4;              // node quad index  (nodes ty*4..ty*4+3)
    const int hp = blockIdx.y;          // head pair (heads hp*2, hp*2+1)
    const int n0 = blockIdx.x * TBN;

    // load W transposed: ws[k][j] = W[(hp*64+j)*DI + k]; coalesced global reads
    for (int idx = t; idx < 64 * DI; idx += 256) {
        int j = idx >> 7;          // 0..63
        int k = idx & 127;
        ws[k * WS_STRIDE + j] = W[(size_t)(hp * 64 + j) * DI + k];
    }
    // stage H_in rows (float4, zero-fill past N)
    {
        const float4* Hv = (const float4*)(Hin + (size_t)n0 * DI);
        float4* hv = (float4*)hs;
        for (int idx = t; idx < TBN * (DI / 4); idx += 256) {
            int node = idx >> 5;   // DI/4 = 32 vecs per node
            float4 v = (n0 + node < NN) ? Hv[idx] : make_float4(0.f, 0.f, 0.f, 0.f);
            hv[idx] = v;
        }
    }
    __syncthreads();

    float acc[4][4];
#pragma unroll
    for (int a = 0; a < 4; a++)
#pragma unroll
        for (int b = 0; b < 4; b++) acc[a][b] = 0.f;

#pragma unroll 4
    for (int k = 0; k < DI; k++) {
        float4 w = *(const float4*)(ws + k * WS_STRIDE + tx * 4);
#pragma unroll
        for (int ni = 0; ni < 4; ni++) {
            float hv = hs[(ty * 4 + ni) * DI + k];
            acc[ni][0] += hv * w.x;
            acc[ni][1] += hv * w.y;
            acc[ni][2] += hv * w.z;
            acc[ni][3] += hv * w.w;
        }
    }

    const int j0   = tx * 4;
    const int head = hp * 2 + (j0 >> 5);
    const int o0   = j0 & 31;
    const float4 as = *(const float4*)&Asrc[head * DO + o0];
    const float4 at = *(const float4*)&Atgt[head * DO + o0];

#pragma unroll
    for (int ni = 0; ni < 4; ni++) {
        int node = n0 + ty * 4 + ni;
        float ps = acc[ni][0] * as.x + acc[ni][1] * as.y + acc[ni][2] * as.z + acc[ni][3] * as.w;
        float pt = acc[ni][0] * at.x + acc[ni][1] * at.y + acc[ni][2] * at.z + acc[ni][3] * at.w;
        // reduce over the 8 lanes (tx 0..7 / 8..15) that share one head+node
#pragma unroll
        for (int off = 1; off < 8; off <<= 1) {
            ps += __shfl_xor_sync(0xffffffffu, ps, off);
            pt += __shfl_xor_sync(0xffffffffu, pt, off);
        }
        if (node < NN) {
            *(float4*)&g_Hw[((size_t)head * NN + node) * DO + o0] =
                make_float4(acc[ni][0], acc[ni][1], acc[ni][2], acc[ni][3]);
            if ((tx & 7) == 0) {
                g_ssrc[head * NN + node] = ps;
                g_stgt[head * NN + node] = pt;
            }
        }
    }
}

// -------- kernel B: per-edge logits (leaky relu) + segment max --------
__global__ __launch_bounds__(256) void k_logits(const int* __restrict__ ei) {
    int e = blockIdx.x * blockDim.x + threadIdx.x;
    if (e >= NE) return;
    int src = clampN(ei[e]);
    int tgt = clampN(ei[NE + e]);
    float4 ev;
    float* evp = &ev.x;
#pragma unroll
    for (int h = 0; h < NH; h++) {
        float v = g_ssrc[h * NN + src] + g_stgt[h * NN + tgt];
        v = v > 0.f ? v : 0.2f * v;
        evp[h] = v;
        atomicMax(&g_segmax[h * NN + tgt], f_enc(v));
    }
    *(float4*)&g_Ee[(size_t)e * 4] = ev;
}

// -------- kernel C: exp(e - max) + segment sum --------
__global__ __launch_bounds__(256) void k_expsum(const int* __restrict__ ei) {
    int e = blockIdx.x * blockDim.x + threadIdx.x;
    if (e >= NE) return;
    int tgt = clampN(ei[NE + e]);
    float4 ev = *(const float4*)&g_Ee[(size_t)e * 4];
    float* evp = &ev.x;
#pragma unroll
    for (int h = 0; h < NH; h++) {
        float m = f_dec(g_segmax[h * NN + tgt]);
        float x = __expf(evp[h] - m);
        evp[h] = x;
        atomicAdd(&g_segsum[h * NN + tgt], x);
    }
    *(float4*)&g_Ee[(size_t)e * 4] = ev;
}

// -------- kernel D: alpha-weighted scatter-sum. one warp per edge --------
// lane -> (head = lane>>3, out quad o = (lane&7)*4); 4 scalar REDG per lane
// (atomicAdd with unused result lowers to red.global.add.f32).
__global__ __launch_bounds__(256) void k_agg(const int* __restrict__ ei,
                                             float* __restrict__ out) {
    int gwarp = (blockIdx.x * blockDim.x + threadIdx.x) >> 5;
    if (gwarp >= NE) return;
    int lane = threadIdx.x & 31;
    int e = gwarp;
    int src = clampN(ei[e]);       // broadcast
    int tgt = clampN(ei[NE + e]);  // broadcast
    int h = lane >> 3;
    int o = (lane & 7) * 4;

    float aexp = g_Ee[(size_t)e * 4 + h];
    float asum = g_segsum[h * NN + tgt];
    float alpha = aexp / asum;

    const float4 hw = *(const float4*)&g_Hw[((size_t)h * NN + src) * DO + o];

    float* dst = &out[((size_t)h * NN + tgt) * DO + o];
    atomicAdd(dst + 0, alpha * hw.x);
    atomicAdd(dst + 1, alpha * hw.y);
    atomicAdd(dst + 2, alpha * hw.z);
    atomicAdd(dst + 3, alpha * hw.w);
}

// -------- kernel E: ELU in place --------
__global__ void k_elu(float* __restrict__ out) {
    int stride = gridDim.x * blockDim.x;
    const int total = NH * NN * DO;
    for (int i = blockIdx.x * blockDim.x + threadIdx.x; i < total; i += stride) {
        float x = out[i];
        out[i] = x > 0.f ? x : expm1f(x);
    }
}

extern "C" void kernel_launch(void* const* d_in, const int* in_sizes, int n_in,
                              void* d_out, int out_size) {
    const float* Hin  = (const float*)d_in[0];
    const int*   ei   = (const int*)d_in[1];     // int32 edge_index [2][NE]
    const float* W    = (const float*)d_in[2];
    const float* Asrc = (const float*)d_in[3];
    const float* Atgt = (const float*)d_in[4];
    float* out = (float*)d_out;

    (void)in_sizes; (void)n_in; (void)out_size;

    k_init<<<1024, 256>>>(out);

    const int smem = (DI * WS_STRIDE + TBN * DI) * (int)sizeof(float); // ~66.5 KB
    cudaFuncSetAttribute(k_gemm, cudaFuncAttributeMaxDynamicSharedMemorySize, smem);
    dim3 gA((NN + TBN - 1) / TBN, 2);
    k_gemm<<<gA, 256, smem>>>(Hin, W, Asrc, Atgt);

    k_logits<<<(NE + 255) / 256, 256>>>(ei);
    k_expsum<<<(NE + 255) / 256, 256>>>(ei);
    k_agg<<<(NE * 32) / 256, 256>>>(ei, out);
    k_elu<<<2048, 256>>>(out);
}

// round 5
// speedup vs baseline: 2.1103x; 2.1103x over previous
#include <cuda_runtime.h>
#include <cstdint>
#include <cstddef>

#define NN 100000
#define NE 1600000
#define NH 4
#define DI 128
#define DO 32

// -------- scratch (no allocs allowed) --------
__device__ float g_Hw[(size_t)NH * NN * DO];   // [h][n][o]  51.2 MB
__device__ float g_ssrc[NN * NH];              // [n][h]  (16B per node)
__device__ float g_stgt[NN * NH];
__device__ int   g_cnt[NN];                    // in-degree histogram
__device__ int   g_fill[NN];                   // scatter cursors
__device__ int   g_rowptr[NN + 1];             // CSR row pointers (by target)
__device__ int   g_esrc[NE];                   // src node id, grouped by target

__device__ __forceinline__ int clampN(int v) {
    v = v < 0 ? 0 : v;
    return v >= NN ? NN - 1 : v;
}

// -------- kernel 0: zero counters --------
__global__ void k_init() {
    int i = blockIdx.x * blockDim.x + threadIdx.x;
    if (i < NN) { g_cnt[i] = 0; g_fill[i] = 0; }
}

// -------- kernel A: H_w = H_in @ W^T (per head) + fused s_src/s_tgt --------
#define TBN 64
#define WS_STRIDE 68
__global__ __launch_bounds__(256) void k_gemm(const float* __restrict__ Hin,
                                              const float* __restrict__ W,
                                              const float* __restrict__ Asrc,
                                              const float* __restrict__ Atgt) {
    extern __shared__ float sm[];
    float* ws = sm;                     // [DI][WS_STRIDE] (uses first 64 cols)
    float* hs = sm + DI * WS_STRIDE;    // [TBN][DI]

    const int t  = threadIdx.x;
    const int tx = t & 15;              // output quad index (j = tx*4)
    const int ty = t >> 4;              // node quad index
    const int hp = blockIdx.y;          // head pair
    const int n0 = blockIdx.x * TBN;

    for (int idx = t; idx < 64 * DI; idx += 256) {
        int j = idx >> 7;
        int k = idx & 127;
        ws[k * WS_STRIDE + j] = W[(size_t)(hp * 64 + j) * DI + k];
    }
    {
        const float4* Hv = (const float4*)(Hin + (size_t)n0 * DI);
        float4* hv = (float4*)hs;
        for (int idx = t; idx < TBN * (DI / 4); idx += 256) {
            int node = idx >> 5;
            float4 v = (n0 + node < NN) ? Hv[idx] : make_float4(0.f, 0.f, 0.f, 0.f);
            hv[idx] = v;
        }
    }
    __syncthreads();

    float acc[4][4];
#pragma unroll
    for (int a = 0; a < 4; a++)
#pragma unroll
        for (int b = 0; b < 4; b++) acc[a][b] = 0.f;

#pragma unroll 4
    for (int k = 0; k < DI; k++) {
        float4 w = *(const float4*)(ws + k * WS_STRIDE + tx * 4);
#pragma unroll
        for (int ni = 0; ni < 4; ni++) {
            float hv = hs[(ty * 4 + ni) * DI + k];
            acc[ni][0] += hv * w.x;
            acc[ni][1] += hv * w.y;
            acc[ni][2] += hv * w.z;
            acc[ni][3] += hv * w.w;
        }
    }

    const int j0   = tx * 4;
    const int head = hp * 2 + (j0 >> 5);
    const int o0   = j0 & 31;
    const float4 as = *(const float4*)&Asrc[head * DO + o0];
    const float4 at = *(const float4*)&Atgt[head * DO + o0];

#pragma unroll
    for (int ni = 0; ni < 4; ni++) {
        int node = n0 + ty * 4 + ni;
        float ps = acc[ni][0] * as.x + acc[ni][1] * as.y + acc[ni][2] * as.z + acc[ni][3] * as.w;
        float pt = acc[ni][0] * at.x + acc[ni][1] * at.y + acc[ni][2] * at.z + acc[ni][3] * at.w;
#pragma unroll
        for (int off = 1; off < 8; off <<= 1) {
            ps += __shfl_xor_sync(0xffffffffu, ps, off);
            pt += __shfl_xor_sync(0xffffffffu, pt, off);
        }
        if (node < NN) {
            *(float4*)&g_Hw[((size_t)head * NN + node) * DO + o0] =
                make_float4(acc[ni][0], acc[ni][1], acc[ni][2], acc[ni][3]);
            if ((tx & 7) == 0) {               // one writer per (node, head)
                g_ssrc[node * NH + head] = ps;
                g_stgt[node * NH + head] = pt;
            }
        }
    }
}

// -------- CSR build: histogram, scan, scatter --------
__global__ __launch_bounds__(256) void k_hist(const int* __restrict__ ei) {
    int e = blockIdx.x * blockDim.x + threadIdx.x;
    if (e >= NE) return;
    atomicAdd(&g_cnt[clampN(ei[NE + e])], 1);
}

__global__ __launch_bounds__(1024) void k_scan() {   // <<<1, 1024>>>
    __shared__ int part[1024];
    int tid = threadIdx.x;
    const int per = (NN + 1023) >> 10;               // 98
    int b = tid * per;
    int e = min(b + per, NN);
    int s = 0;
    for (int i = b; i < e; i++) s += g_cnt[i];
    part[tid] = s;
    __syncthreads();
    for (int off = 1; off < 1024; off <<= 1) {
        int v = (tid >= off) ? part[tid - off] : 0;
        __syncthreads();
        part[tid] += v;
        __syncthreads();
    }
    int run = part[tid] - s;                          // exclusive prefix
    for (int i = b; i < e; i++) { g_rowptr[i] = run; run += g_cnt[i]; }
    if (tid == 1023) g_rowptr[NN] = run;              // == NE
}

__global__ __launch_bounds__(256) void k_scatter(const int* __restrict__ ei) {
    int e = blockIdx.x * blockDim.x + threadIdx.x;
    if (e >= NE) return;
    int src = clampN(ei[e]);
    int tgt = clampN(ei[NE + e]);
    int pos = g_rowptr[tgt] + atomicAdd(&g_fill[tgt], 1);
    g_esrc[pos] = src;
}

// -------- kernel D: gather aggregation. one warp per target node --------
// lane -> (head = lane>>3, out quad o = (lane&7)*4). Softmax computed on the
// fly (no max subtraction: |logit| <~ 25, exp safe in fp32). Zero atomics;
// output written exactly once.
__global__ __launch_bounds__(256) void k_agg(float* __restrict__ out) {
    int tgt = (blockIdx.x * blockDim.x + threadIdx.x) >> 5;
    if (tgt >= NN) return;
    int lane = threadIdx.x & 31;
    int h = lane >> 3;
    int o = (lane & 7) * 4;

    int beg = g_rowptr[tgt];
    int end = g_rowptr[tgt + 1];

    float4* dst = (float4*)&out[((size_t)h * NN + tgt) * DO + o];

    if (beg == end) {                       // isolated node: elu(0) = 0
        *dst = make_float4(0.f, 0.f, 0.f, 0.f);
        return;
    }

    float st = g_stgt[tgt * NH + h];
    float4 acc = make_float4(0.f, 0.f, 0.f, 0.f);
    float sum = 0.f;

    for (int i = beg; i < end; i++) {
        int src = g_esrc[i];                              // warp-broadcast
        float ss = g_ssrc[src * NH + h];                  // 16B sector / edge
        float E  = ss + st;
        E = E > 0.f ? E : 0.2f * E;
        float x = __expf(E);
        sum += x;
        const float4 hw = *(const float4*)&g_Hw[((size_t)h * NN + src) * DO + o];
        acc.x += x * hw.x;
        acc.y += x * hw.y;
        acc.z += x * hw.z;
        acc.w += x * hw.w;
    }

    float inv = 1.0f / sum;
    float4 r;
    r.x = acc.x * inv; r.y = acc.y * inv; r.z = acc.z * inv; r.w = acc.w * inv;
    r.x = r.x > 0.f ? r.x : expm1f(r.x);
    r.y = r.y > 0.f ? r.y : expm1f(r.y);
    r.z = r.z > 0.f ? r.z : expm1f(r.z);
    r.w = r.w > 0.f ? r.w : expm1f(r.w);
    *dst = r;
}

extern "C" void kernel_launch(void* const* d_in, const int* in_sizes, int n_in,
                              void* d_out, int out_size) {
    const float* Hin  = (const float*)d_in[0];
    const int*   ei   = (const int*)d_in[1];     // int32 edge_index [2][NE]
    const float* W    = (const float*)d_in[2];
    const float* Asrc = (const float*)d_in[3];
    const float* Atgt = (const float*)d_in[4];
    float* out = (float*)d_out;

    (void)in_sizes; (void)n_in; (void)out_size;

    k_init<<<(NN + 255) / 256, 256>>>();

    const int smem = (DI * WS_STRIDE + TBN * DI) * (int)sizeof(float); // ~66.5 KB
    cudaFuncSetAttribute(k_gemm, cudaFuncAttributeMaxDynamicSharedMemorySize, smem);
    dim3 gA((NN + TBN - 1) / TBN, 2);
    k_gemm<<<gA, 256, smem>>>(Hin, W, Asrc, Atgt);

    k_hist<<<(NE + 255) / 256, 256>>>(ei);
    k_scan<<<1, 1024>>>();
    k_scatter<<<(NE + 255) / 256, 256>>>(ei);

    // 8 warps / block, one warp per target node
    k_agg<<<(NN + 7) / 8, 256>>>(out);
}

// round 6
// speedup vs baseline: 2.9404x; 1.3933x over previous
#include <cuda_runtime.h>
#include <cstdint>
#include <cstddef>

#define NN 100000
#define NE 1600000
#define NH 4
#define DI 128
#define DO 32

#define SCB 512                       // cnt elems per scan block
#define NSB ((NN + SCB - 1) / SCB)    // 196 scan blocks

// -------- scratch (no allocs allowed) --------
__device__ float g_Hw[(size_t)NH * NN * DO];   // [h][n][o]  51.2 MB
__device__ float g_ssrc[NN * NH];              // [n][h]  (16B per node)
__device__ float g_stgt[NN * NH];
__device__ int   g_cnt[NN];                    // in-degree histogram
__device__ int   g_fill[NN];                   // scatter cursors
__device__ int   g_rowptr[NN + 1];             // CSR row pointers (by target)
__device__ int   g_esrc[NE];                   // src node id, grouped by target
__device__ int   g_bsum[NSB];                  // per-block chunk sums
__device__ int   g_boff[NSB];                  // exclusive prefix of chunk sums

__device__ __forceinline__ int clampN(int v) {
    v = v < 0 ? 0 : v;
    return v >= NN ? NN - 1 : v;
}

// -------- kernel 0: zero counters --------
__global__ void k_init() {
    int i = blockIdx.x * blockDim.x + threadIdx.x;
    if (i < NN) { g_cnt[i] = 0; g_fill[i] = 0; }
    if (i == 0) g_rowptr[NN] = NE;     // total is a compile-time constant
}

// -------- kernel A: H_w = H_in @ W^T (per head) + fused s_src/s_tgt --------
#define TBN 64
#define WS_STRIDE 68
__global__ __launch_bounds__(256) void k_gemm(const float* __restrict__ Hin,
                                              const float* __restrict__ W,
                                              const float* __restrict__ Asrc,
                                              const float* __restrict__ Atgt) {
    extern __shared__ float sm[];
    float* ws = sm;                     // [DI][WS_STRIDE] (uses first 64 cols)
    float* hs = sm + DI * WS_STRIDE;    // [TBN][DI]

    const int t  = threadIdx.x;
    const int tx = t & 15;              // output quad index (j = tx*4)
    const int ty = t >> 4;              // node quad index
    const int hp = blockIdx.y;          // head pair
    const int n0 = blockIdx.x * TBN;

    for (int idx = t; idx < 64 * DI; idx += 256) {
        int j = idx >> 7;
        int k = idx & 127;
        ws[k * WS_STRIDE + j] = W[(size_t)(hp * 64 + j) * DI + k];
    }
    {
        const float4* Hv = (const float4*)(Hin + (size_t)n0 * DI);
        float4* hv = (float4*)hs;
        for (int idx = t; idx < TBN * (DI / 4); idx += 256) {
            int node = idx >> 5;
            float4 v = (n0 + node < NN) ? Hv[idx] : make_float4(0.f, 0.f, 0.f, 0.f);
            hv[idx] = v;
        }
    }
    __syncthreads();

    float acc[4][4];
#pragma unroll
    for (int a = 0; a < 4; a++)
#pragma unroll
        for (int b = 0; b < 4; b++) acc[a][b] = 0.f;

#pragma unroll 4
    for (int k = 0; k < DI; k++) {
        float4 w = *(const float4*)(ws + k * WS_STRIDE + tx * 4);
#pragma unroll
        for (int ni = 0; ni < 4; ni++) {
            float hv = hs[(ty * 4 + ni) * DI + k];
            acc[ni][0] += hv * w.x;
            acc[ni][1] += hv * w.y;
            acc[ni][2] += hv * w.z;
            acc[ni][3] += hv * w.w;
        }
    }

    const int j0   = tx * 4;
    const int head = hp * 2 + (j0 >> 5);
    const int o0   = j0 & 31;
    const float4 as = *(const float4*)&Asrc[head * DO + o0];
    const float4 at = *(const float4*)&Atgt[head * DO + o0];

#pragma unroll
    for (int ni = 0; ni < 4; ni++) {
        int node = n0 + ty * 4 + ni;
        float ps = acc[ni][0] * as.x + acc[ni][1] * as.y + acc[ni][2] * as.z + acc[ni][3] * as.w;
        float pt = acc[ni][0] * at.x + acc[ni][1] * at.y + acc[ni][2] * at.z + acc[ni][3] * at.w;
#pragma unroll
        for (int off = 1; off < 8; off <<= 1) {
            ps += __shfl_xor_sync(0xffffffffu, ps, off);
            pt += __shfl_xor_sync(0xffffffffu, pt, off);
        }
        if (node < NN) {
            *(float4*)&g_Hw[((size_t)head * NN + node) * DO + o0] =
                make_float4(acc[ni][0], acc[ni][1], acc[ni][2], acc[ni][3]);
            if ((tx & 7) == 0) {               // one writer per (node, head)
                g_ssrc[node * NH + head] = ps;
                g_stgt[node * NH + head] = pt;
            }
        }
    }
}

// -------- CSR build: histogram, 3-phase scan, scatter --------
__global__ __launch_bounds__(256) void k_hist(const int* __restrict__ ei) {
    int e = blockIdx.x * blockDim.x + threadIdx.x;
    if (e >= NE) return;
    atomicAdd(&g_cnt[clampN(ei[NE + e])], 1);
}

// phase 1: per-block chunk sums
__global__ __launch_bounds__(256) void k_scan1() {
    int t = threadIdx.x;
    int i0 = blockIdx.x * SCB + t * 2;
    int v0 = (i0     < NN) ? g_cnt[i0]     : 0;
    int v1 = (i0 + 1 < NN) ? g_cnt[i0 + 1] : 0;
    int s = v0 + v1;
#pragma unroll
    for (int off = 16; off > 0; off >>= 1) s += __shfl_xor_sync(0xffffffffu, s, off);
    __shared__ int ws[8];
    if ((t & 31) == 0) ws[t >> 5] = s;
    __syncthreads();
    if (t == 0) {
        int tot = 0;
#pragma unroll
        for (int w = 0; w < 8; w++) tot += ws[w];
        g_bsum[blockIdx.x] = tot;
    }
}

// phase 2: exclusive scan of the NSB (=196) partials in one block
__global__ __launch_bounds__(256) void k_scan2() {
    int t = threadIdx.x;
    int v = (t < NSB) ? g_bsum[t] : 0;
    int x = v;
    int lane = t & 31, warp = t >> 5;
#pragma unroll
    for (int off = 1; off < 32; off <<= 1) {
        int y = __shfl_up_sync(0xffffffffu, x, off);
        if (lane >= off) x += y;
    }
    __shared__ int ws[8];
    if (lane == 31) ws[warp] = x;
    __syncthreads();
    if (warp == 0) {
        int w = (lane < 8) ? ws[lane] : 0;
#pragma unroll
        for (int off = 1; off < 8; off <<= 1) {
            int y = __shfl_up_sync(0xffffffffu, w, off);
            if (lane >= off) w += y;
        }
        if (lane < 8) ws[lane] = w;
    }
    __syncthreads();
    int base = (warp > 0) ? ws[warp - 1] : 0;
    if (t < NSB) g_boff[t] = base + x - v;   // exclusive prefix
}

// phase 3: block-local exclusive scan + block offset -> rowptr
__global__ __launch_bounds__(256) void k_scan3() {
    int t = threadIdx.x;
    int i0 = blockIdx.x * SCB + t * 2;
    int v0 = (i0     < NN) ? g_cnt[i0]     : 0;
    int v1 = (i0 + 1 < NN) ? g_cnt[i0 + 1] : 0;
    int tsum = v0 + v1;

    int x = tsum;
    int lane = t & 31, warp = t >> 5;
#pragma unroll
    for (int off = 1; off < 32; off <<= 1) {
        int y = __shfl_up_sync(0xffffffffu, x, off);
        if (lane >= off) x += y;
    }
    __shared__ int ws[8];
    if (lane == 31) ws[warp] = x;
    __syncthreads();
    if (warp == 0) {
        int w = (lane < 8) ? ws[lane] : 0;
#pragma unroll
        for (int off = 1; off < 8; off <<= 1) {
            int y = __shfl_up_sync(0xffffffffu, w, off);
            if (lane >= off) w += y;
        }
        if (lane < 8) ws[lane] = w;
    }
    __syncthreads();
    int wbase = (warp > 0) ? ws[warp - 1] : 0;
    int excl = g_boff[blockIdx.x] + wbase + x - tsum;

    if (i0     < NN) g_rowptr[i0]     = excl;
    if (i0 + 1 < NN) g_rowptr[i0 + 1] = excl + v0;
}

__global__ __launch_bounds__(256) void k_scatter(const int* __restrict__ ei) {
    int e = blockIdx.x * blockDim.x + threadIdx.x;
    if (e >= NE) return;
    int src = clampN(ei[e]);
    int tgt = clampN(ei[NE + e]);
    int pos = g_rowptr[tgt] + atomicAdd(&g_fill[tgt], 1);
    g_esrc[pos] = src;
}

// -------- kernel D: gather aggregation. one warp per target node --------
__global__ __launch_bounds__(256) void k_agg(float* __restrict__ out) {
    int tgt = (blockIdx.x * blockDim.x + threadIdx.x) >> 5;
    if (tgt >= NN) return;
    int lane = threadIdx.x & 31;
    int h = lane >> 3;
    int o = (lane & 7) * 4;

    int beg = g_rowptr[tgt];
    int end = g_rowptr[tgt + 1];

    float4* dst = (float4*)&out[((size_t)h * NN + tgt) * DO + o];

    if (beg == end) {                       // isolated node: elu(0) = 0
        *dst = make_float4(0.f, 0.f, 0.f, 0.f);
        return;
    }

    float st = g_stgt[tgt * NH + h];
    float4 acc = make_float4(0.f, 0.f, 0.f, 0.f);
    float sum = 0.f;

    for (int i = beg; i < end; i++) {
        int src = g_esrc[i];                              // warp-broadcast
        float ss = g_ssrc[src * NH + h];                  // 16B sector / edge
        float E  = ss + st;
        E = E > 0.f ? E : 0.2f * E;
        float x = __expf(E);
        sum += x;
        const float4 hw = *(const float4*)&g_Hw[((size_t)h * NN + src) * DO + o];
        acc.x += x * hw.x;
        acc.y += x * hw.y;
        acc.z += x * hw.z;
        acc.w += x * hw.w;
    }

    float inv = 1.0f / sum;
    float4 r;
    r.x = acc.x * inv; r.y = acc.y * inv; r.z = acc.z * inv; r.w = acc.w * inv;
    r.x = r.x > 0.f ? r.x : expm1f(r.x);
    r.y = r.y > 0.f ? r.y : expm1f(r.y);
    r.z = r.z > 0.f ? r.z : expm1f(r.z);
    r.w = r.w > 0.f ? r.w : expm1f(r.w);
    *dst = r;
}

extern "C" void kernel_launch(void* const* d_in, const int* in_sizes, int n_in,
                              void* d_out, int out_size) {
    const float* Hin  = (const float*)d_in[0];
    const int*   ei   = (const int*)d_in[1];     // int32 edge_index [2][NE]
    const float* W    = (const float*)d_in[2];
    const float* Asrc = (const float*)d_in[3];
    const float* Atgt = (const float*)d_in[4];
    float* out = (float*)d_out;

    (void)in_sizes; (void)n_in; (void)out_size;

    k_init<<<(NN + 255) / 256, 256>>>();

    const int smem = (DI * WS_STRIDE + TBN * DI) * (int)sizeof(float); // ~66.5 KB
    cudaFuncSetAttribute(k_gemm, cudaFuncAttributeMaxDynamicSharedMemorySize, smem);
    dim3 gA((NN + TBN - 1) / TBN, 2);
    k_gemm<<<gA, 256, smem>>>(Hin, W, Asrc, Atgt);

    k_hist<<<(NE + 255) / 256, 256>>>(ei);
    k_scan1<<<NSB, 256>>>();
    k_scan2<<<1, 256>>>();
    k_scan3<<<NSB, 256>>>();
    k_scatter<<<(NE + 255) / 256, 256>>>(ei);

    // 8 warps / block, one warp per target node
    k_agg<<<(NN + 7) / 8, 256>>>(out);
}

// round 10
// speedup vs baseline: 3.8346x; 1.3041x over previous
#include <cuda_runtime.h>
#include <cuda_bf16.h>
#include <cstdint>
#include <cstddef>

#define NN 100000
#define NE 1600000
#define NH 4
#define DI 128
#define DO 32

#define SCB 512
#define NSB ((NN + SCB - 1) / SCB)    // 196 scan blocks

#define GT 128                         // gemm tile: nodes per CTA
#define NTILE ((NN + GT - 1) / GT)     // 782 CTAs

// -------- scratch (no allocs allowed) --------
__device__ float g_Hw[(size_t)NH * NN * DO];   // [h][n][o]  51.2 MB
__device__ float g_ssrc[NN * NH];              // [n][h]
__device__ float g_stgt[NN * NH];
__device__ int   g_cnt[NN];
__device__ int   g_fill[NN];
__device__ int   g_rowptr[NN + 1];
__device__ int   g_esrc[NE];
__device__ int   g_bsum[NSB];
__device__ int   g_boff[NSB];

__device__ __forceinline__ int clampN(int v) {
    v = v < 0 ? 0 : v;
    return v >= NN ? NN - 1 : v;
}

// -------- kernel 0 --------
__global__ void k_init() {
    int i = blockIdx.x * blockDim.x + threadIdx.x;
    if (i < NN) { g_cnt[i] = 0; g_fill[i] = 0; }
    if (i == 0) g_rowptr[NN] = NE;
}

// ===== mma.sync bf16 helpers (baseline sm_80+ ISA; no 'a'-features) =====
__device__ __forceinline__ void bf16_split(float x, float y, uint32_t& hi, uint32_t& lo) {
    __nv_bfloat162 h = __floats2bfloat162_rn(x, y);        // .x=lo16 holds x
    float hx = __bfloat162float(h.x), hy = __bfloat162float(h.y);
    __nv_bfloat162 l = __floats2bfloat162_rn(x - hx, y - hy);
    hi = *(uint32_t*)&h;
    lo = *(uint32_t*)&l;
}
__device__ __forceinline__ void mma16816(float* c, const uint32_t* a, const uint32_t* b) {
    asm volatile(
        "mma.sync.aligned.m16n8k16.row.col.f32.bf16.bf16.f32 "
        "{%0,%1,%2,%3}, {%4,%5,%6,%7}, {%8,%9}, {%0,%1,%2,%3};"
        : "+f"(c[0]), "+f"(c[1]), "+f"(c[2]), "+f"(c[3])
        : "r"(a[0]), "r"(a[1]), "r"(a[2]), "r"(a[3]), "r"(b[0]), "r"(b[1]));
}

// -------- kernel A: bf16x2-split tensor-core GEMM + fused s_src/s_tgt --------
// CTA: 128 nodes x 128 outputs, K=128. 8 warps: warp_m = wid&3 (32 rows),
// warp_n = wid>>2 (64 cols = 2 heads). 3-term split: hi*hi + hi*lo + lo*hi.
__global__ __launch_bounds__(256) void k_gemm(const float* __restrict__ Hin,
                                              const float* __restrict__ W,
                                              const float* __restrict__ Asrc,
                                              const float* __restrict__ Atgt) {
    const int t = threadIdx.x;
    const int wid = t >> 5, lane = t & 31;
    const int warp_m = wid & 3, warp_n = wid >> 2;
    const int qr = lane >> 2, qc = lane & 3;      // quad row / quad col
    const int nb = blockIdx.x * GT + warp_m * 32; // first node of warp tile

    float C[2][8][4];
#pragma unroll
    for (int mt = 0; mt < 2; mt++)
#pragma unroll
        for (int nt = 0; nt < 8; nt++)
#pragma unroll
            for (int q = 0; q < 4; q++) C[mt][nt][q] = 0.f;

#pragma unroll
    for (int kk = 0; kk < 8; kk++) {
        const int k0 = kk * 16 + qc * 2;

        // A fragments (2 m-tiles), hi/lo split, direct from global
        uint32_t Ah[2][4], Al[2][4];
#pragma unroll
        for (int mt = 0; mt < 2; mt++) {
            int r0 = nb + mt * 16 + qr;
            int r1 = r0 + 8;
            r0 = r0 < NN ? r0 : NN - 1;           // clamped loads; stores guarded
            r1 = r1 < NN ? r1 : NN - 1;
            const float* p0 = Hin + (size_t)r0 * DI + k0;
            const float* p1 = Hin + (size_t)r1 * DI + k0;
            float2 v;
            v = *(const float2*)p0;       bf16_split(v.x, v.y, Ah[mt][0], Al[mt][0]);
            v = *(const float2*)p1;       bf16_split(v.x, v.y, Ah[mt][1], Al[mt][1]);
            v = *(const float2*)(p0 + 8); bf16_split(v.x, v.y, Ah[mt][2], Al[mt][2]);
            v = *(const float2*)(p1 + 8); bf16_split(v.x, v.y, Ah[mt][3], Al[mt][3]);
        }

#pragma unroll
        for (int nt = 0; nt < 8; nt++) {
            const int j = warp_n * 64 + nt * 8 + qr;   // B n-index
            const float* pb = W + (size_t)j * DI + k0;
            uint32_t Bh[2], Bl[2];
            float2 v;
            v = *(const float2*)pb;       bf16_split(v.x, v.y, Bh[0], Bl[0]);
            v = *(const float2*)(pb + 8); bf16_split(v.x, v.y, Bh[1], Bl[1]);
#pragma unroll
            for (int mt = 0; mt < 2; mt++) {
                mma16816(C[mt][nt], Ah[mt], Bh);
                mma16816(C[mt][nt], Ah[mt], Bl);
                mma16816(C[mt][nt], Al[mt], Bh);
            }
        }
    }

    // ---- epilogue: store H_w + fused attention-logit dots ----
    // C frag: regs {0,1} = row qr, cols qc*2,+1; regs {2,3} = row qr+8.
    // Flat j = h*32 + o, so Asrc[j]/Atgt[j] index directly.
    const int h0 = warp_n * 2;

    // hoist attention-vector loads (same for all mt/rh)
    float a0v[8], a1v[8], b0v[8], b1v[8];
#pragma unroll
    for (int nt = 0; nt < 8; nt++) {
        const int j = warp_n * 64 + nt * 8 + qc * 2;
        a0v[nt] = __ldg(&Asrc[j]); a1v[nt] = __ldg(&Asrc[j + 1]);
        b0v[nt] = __ldg(&Atgt[j]); b1v[nt] = __ldg(&Atgt[j + 1]);
    }

#pragma unroll
    for (int mt = 0; mt < 2; mt++) {
#pragma unroll
        for (int rh = 0; rh < 2; rh++) {
            const int node = nb + mt * 16 + qr + rh * 8;
            float ps0 = 0.f, ps1 = 0.f, pt0 = 0.f, pt1 = 0.f;
#pragma unroll
            for (int nt = 0; nt < 8; nt++) {
                const float c0 = C[mt][nt][rh * 2], c1 = C[mt][nt][rh * 2 + 1];
                if (nt < 4) { ps0 += c0 * a0v[nt] + c1 * a1v[nt]; pt0 += c0 * b0v[nt] + c1 * b1v[nt]; }
                else        { ps1 += c0 * a0v[nt] + c1 * a1v[nt]; pt1 += c0 * b0v[nt] + c1 * b1v[nt]; }
                if (node < NN) {
                    const int h = h0 + (nt >> 2);
                    const int o = (nt & 3) * 8 + qc * 2;
                    *(float2*)&g_Hw[((size_t)h * NN + node) * DO + o] = make_float2(c0, c1);
                }
            }
#pragma unroll
            for (int d = 1; d < 4; d <<= 1) {
                ps0 += __shfl_xor_sync(0xffffffffu, ps0, d);
                ps1 += __shfl_xor_sync(0xffffffffu, ps1, d);
                pt0 += __shfl_xor_sync(0xffffffffu, pt0, d);
                pt1 += __shfl_xor_sync(0xffffffffu, pt1, d);
            }
            if (qc == 0 && node < NN) {
                g_ssrc[node * NH + h0]     = ps0;
                g_ssrc[node * NH + h0 + 1] = ps1;
                g_stgt[node * NH + h0]     = pt0;
                g_stgt[node * NH + h0 + 1] = pt1;
            }
        }
    }
}

// -------- CSR build --------
__global__ __launch_bounds__(256) void k_hist(const int* __restrict__ ei) {
    int e = blockIdx.x * blockDim.x + threadIdx.x;
    if (e >= NE) return;
    atomicAdd(&g_cnt[clampN(ei[NE + e])], 1);
}

__global__ __launch_bounds__(256) void k_scan1() {
    int t = threadIdx.x;
    int i0 = blockIdx.x * SCB + t * 2;
    int v0 = (i0     < NN) ? g_cnt[i0]     : 0;
    int v1 = (i0 + 1 < NN) ? g_cnt[i0 + 1] : 0;
    int s = v0 + v1;
#pragma unroll
    for (int off = 16; off > 0; off >>= 1) s += __shfl_xor_sync(0xffffffffu, s, off);
    __shared__ int ws[8];
    if ((t & 31) == 0) ws[t >> 5] = s;
    __syncthreads();
    if (t == 0) {
        int tot = 0;
#pragma unroll
        for (int w = 0; w < 8; w++) tot += ws[w];
        g_bsum[blockIdx.x] = tot;
    }
}

__global__ __launch_bounds__(256) void k_scan2() {
    int t = threadIdx.x;
    int v = (t < NSB) ? g_bsum[t] : 0;
    int x = v;
    int lane = t & 31, warp = t >> 5;
#pragma unroll
    for (int off = 1; off < 32; off <<= 1) {
        int y = __shfl_up_sync(0xffffffffu, x, off);
        if (lane >= off) x += y;
    }
    __shared__ int ws[8];
    if (lane == 31) ws[warp] = x;
    __syncthreads();
    if (warp == 0) {
        int w = (lane < 8) ? ws[lane] : 0;
#pragma unroll
        for (int off = 1; off < 8; off <<= 1) {
            int y = __shfl_up_sync(0xffffffffu, w, off);
            if (lane >= off) w += y;
        }
        if (lane < 8) ws[lane] = w;
    }
    __syncthreads();
    int base = (warp > 0) ? ws[warp - 1] : 0;
    if (t < NSB) g_boff[t] = base + x - v;
}

__global__ __launch_bounds__(256) void k_scan3() {
    int t = threadIdx.x;
    int i0 = blockIdx.x * SCB + t * 2;
    int v0 = (i0     < NN) ? g_cnt[i0]     : 0;
    int v1 = (i0 + 1 < NN) ? g_cnt[i0 + 1] : 0;
    int tsum = v0 + v1;

    int x = tsum;
    int lane = t & 31, warp = t >> 5;
#pragma unroll
    for (int off = 1; off < 32; off <<= 1) {
        int y = __shfl_up_sync(0xffffffffu, x, off);
        if (lane >= off) x += y;
    }
    __shared__ int ws[8];
    if (lane == 31) ws[warp] = x;
    __syncthreads();
    if (warp == 0) {
        int w = (lane < 8) ? ws[lane] : 0;
#pragma unroll
        for (int off = 1; off < 8; off <<= 1) {
            int y = __shfl_up_sync(0xffffffffu, w, off);
            if (lane >= off) w += y;
        }
        if (lane < 8) ws[lane] = w;
    }
    __syncthreads();
    int wbase = (warp > 0) ? ws[warp - 1] : 0;
    int excl = g_boff[blockIdx.x] + wbase + x - tsum;

    if (i0     < NN) g_rowptr[i0]     = excl;
    if (i0 + 1 < NN) g_rowptr[i0 + 1] = excl + v0;
}

__global__ __launch_bounds__(256) void k_scatter(const int* __restrict__ ei) {
    int e = blockIdx.x * blockDim.x + threadIdx.x;
    if (e >= NE) return;
    int src = clampN(ei[e]);
    int tgt = clampN(ei[NE + e]);
    int pos = g_rowptr[tgt] + atomicAdd(&g_fill[tgt], 1);
    g_esrc[pos] = src;
}

// -------- kernel D: gather aggregation, one warp per target node --------
__global__ __launch_bounds__(256) void k_agg(float* __restrict__ out) {
    int tgt = (blockIdx.x * blockDim.x + threadIdx.x) >> 5;
    if (tgt >= NN) return;
    int lane = threadIdx.x & 31;
    int h = lane >> 3;
    int o = (lane & 7) * 4;

    int beg = g_rowptr[tgt];
    int end = g_rowptr[tgt + 1];

    float4* dst = (float4*)&out[((size_t)h * NN + tgt) * DO + o];

    if (beg == end) {
        *dst = make_float4(0.f, 0.f, 0.f, 0.f);
        return;
    }

    float st = g_stgt[tgt * NH + h];
    float4 acc = make_float4(0.f, 0.f, 0.f, 0.f);
    float sum = 0.f;

    for (int i = beg; i < end; i++) {
        int src = g_esrc[i];
        float ss = g_ssrc[src * NH + h];
        float E  = ss + st;
        E = E > 0.f ? E : 0.2f * E;
        float x = __expf(E);
        sum += x;
        const float4 hw = *(const float4*)&g_Hw[((size_t)h * NN + src) * DO + o];
        acc.x += x * hw.x;
        acc.y += x * hw.y;
        acc.z += x * hw.z;
        acc.w += x * hw.w;
    }

    float inv = 1.0f / sum;
    float4 r;
    r.x = acc.x * inv; r.y = acc.y * inv; r.z = acc.z * inv; r.w = acc.w * inv;
    r.x = r.x > 0.f ? r.x : expm1f(r.x);
    r.y = r.y > 0.f ? r.y : expm1f(r.y);
    r.z = r.z > 0.f ? r.z : expm1f(r.z);
    r.w = r.w > 0.f ? r.w : expm1f(r.w);
    *dst = r;
}

extern "C" void kernel_launch(void* const* d_in, const int* in_sizes, int n_in,
                              void* d_out, int out_size) {
    const float* Hin  = (const float*)d_in[0];
    const int*   ei   = (const int*)d_in[1];
    const float* W    = (const float*)d_in[2];
    const float* Asrc = (const float*)d_in[3];
    const float* Atgt = (const float*)d_in[4];
    float* out = (float*)d_out;

    (void)in_sizes; (void)n_in; (void)out_size;

    // launch order chosen so k_gemm is profile index 3
    k_init<<<(NN + 255) / 256, 256>>>();
    k_hist<<<(NE + 255) / 256, 256>>>(ei);
    k_scan1<<<NSB, 256>>>();
    k_gemm<<<NTILE, 256>>>(Hin, W, Asrc, Atgt);
    k_scan2<<<1, 256>>>();
    k_scan3<<<NSB, 256>>>();
    k_scatter<<<(NE + 255) / 256, 256>>>(ei);
    k_agg<<<(NN + 7) / 8, 256>>>(out);
}